// round 17
// baseline (speedup 1.0000x reference)
#include <cuda_runtime.h>

// TBSyntaxParser: B=8192, buffer [B,128,50] f32, W [3,300], b[3],
// legal [B,3], buffer_index [B] i32, stack_indexes [B,3] i32.
// out[B,3] = exp(min(X@W.T+b,10)) * legal, X = 6 gathered rows of 50 floats.
//
// FINAL family (R8 body + vectorized epilogue): two adjacent states per
// warp, NO smem/barrier (W via __ldg, L1-hot), int2-vectorized index loads,
// 12 batched gather LDG.64 in flight, packed fma.rn.f32x2 dot products,
// packed f32x2 shfl butterfly. Epilogue: lanes 0..2 each produce an output
// PAIR (LDG.64 legal pair, 2x __expf, 1x STG.64) -- 3 stores instead of 6,
// no select chain. 296x448 grid = exactly 2 CTAs (28 warps) per SM.

#define HH   50
#define ROWE 25
#define W1   300
#define W2   600
#define CTAS 296
#define THR  448          // 14 warps/CTA, 2 states/warp
#define NSTATES 8192

typedef unsigned long long u64;

__device__ __forceinline__ void ffma2(u64& acc, u64 x, u64 w) {
    asm("fma.rn.f32x2 %0, %1, %2, %3;" : "=l"(acc) : "l"(x), "l"(w), "l"(acc));
}
__device__ __forceinline__ u64 fadd2(u64 a, u64 b) {
    u64 r;
    asm("add.rn.f32x2 %0, %1, %2;" : "=l"(r) : "l"(a), "l"(b));
    return r;
}
__device__ __forceinline__ float fold2(u64 a) {
    float lo, hi;
    asm("mov.b64 {%0,%1}, %2;" : "=f"(lo), "=f"(hi) : "l"(a));
    return lo + hi;
}
__device__ __forceinline__ u64 pack2(float lo, float hi) {
    u64 r;
    asm("mov.b64 %0, {%1,%2};" : "=l"(r) : "f"(lo), "f"(hi));
    return r;
}
__device__ __forceinline__ u64 shfl_xor64(u64 v, int off) {
    unsigned lo = (unsigned)v, hi = (unsigned)(v >> 32);
    lo = __shfl_xor_sync(0xffffffffu, lo, off);
    hi = __shfl_xor_sync(0xffffffffu, hi, off);
    return ((u64)hi << 32) | lo;
}

__global__ __launch_bounds__(THR, 2)
void tb_parser_kernel(const float* __restrict__ buffer,
                      const float* __restrict__ W,
                      const float* __restrict__ bvec,
                      const float* __restrict__ legal,
                      const int*   __restrict__ buf_idx,
                      const int*   __restrict__ stk_idx,
                      float*       __restrict__ out)
{
    const int tid  = threadIdx.x;
    const int warp = tid >> 5;
    const int lane = tid & 31;
    const int gw   = blockIdx.x * 14 + warp;   // 0..4143
    const int sA   = gw * 2;
    if (sA >= NSTATES) return;                 // no barrier: early-out is safe

    // ---- vectorized dependent index loads (4x LDG.64, all 8B-aligned) ----
    const int2 bi2 = __ldg((const int2*)(buf_idx + sA));
    const int2 s01 = __ldg((const int2*)(stk_idx + sA * 3));
    const int2 s23 = __ldg((const int2*)(stk_idx + sA * 3 + 2));
    const int2 s45 = __ldg((const int2*)(stk_idx + sA * 3 + 4));
    const int biA = bi2.x, biB = bi2.y;
    const int aA0 = s01.x, aA1 = s01.y, aA2 = s23.x;
    const int aB0 = s23.y, aB1 = s45.x, aB2 = s45.y;

    // ---- epilogue operands: lanes 0..2 own output pairs (2k, 2k+1) ----
    // pair k covers logits: k=0 -> (A.o0, A.o1); k=1 -> (A.o2, B.o0);
    //                       k=2 -> (B.o1, B.o2)
    float lgx = 0.f, lgy = 0.f, bbx = 0.f, bby = 0.f;
    if (lane < 3) {
        const float2 lp = __ldg((const float2*)(legal + sA * 3 + lane * 2));
        lgx = lp.x; lgy = lp.y;
        // bias for pair k: (b[(2k)%3], b[(2k+1)%3])
        const int i0 = (lane * 2) % 3, i1 = (lane * 2 + 1) % 3;
        bbx = __ldg(bvec + i0);
        bby = __ldg(bvec + i1);
    }

    const int  c  = (lane < ROWE) ? lane : (ROWE - 1);
    const bool on = (lane < ROWE);

    // ---- W loads (independent of idx trip; L1-hot after first touch) ----
    u64 w[6][3];
    #pragma unroll
    for (int r = 0; r < 6; r++) {
        const float* wp = W + r * HH + c * 2;
        w[r][0] = *(const u64*)(wp);
        w[r][1] = *(const u64*)(wp + W1);
        w[r][2] = *(const u64*)(wp + W2);
    }

    // ---- batched gathers: 12 LDG.64 in flight ----
    const float* baseA = buffer + (size_t)sA * (128 * HH) + c * 2;
    const float* baseB = baseA + 128 * HH;

    u64 xA[6], xB[6];
    xA[0] = *(const u64*)(baseA + (biA    ) * HH);
    xA[1] = *(const u64*)(baseA + (biA + 1) * HH);
    xA[2] = *(const u64*)(baseA + (biA + 2) * HH);
    xA[3] = *(const u64*)(baseA + (aA0    ) * HH);
    xA[4] = *(const u64*)(baseA + (aA1    ) * HH);
    xA[5] = *(const u64*)(baseA + (aA2    ) * HH);
    xB[0] = *(const u64*)(baseB + (biB    ) * HH);
    xB[1] = *(const u64*)(baseB + (biB + 1) * HH);
    xB[2] = *(const u64*)(baseB + (biB + 2) * HH);
    xB[3] = *(const u64*)(baseB + (aB0    ) * HH);
    xB[4] = *(const u64*)(baseB + (aB1    ) * HH);
    xB[5] = *(const u64*)(baseB + (aB2    ) * HH);
    if (!on) {
        #pragma unroll
        for (int r = 0; r < 6; r++) { xA[r] = 0ULL; xB[r] = 0ULL; }
    }

    // ---- packed dot products; each W reg feeds both states ----
    u64 a0A = 0, a1A = 0, a2A = 0, a0B = 0, a1B = 0, a2B = 0;
    #pragma unroll
    for (int r = 0; r < 6; r++) {
        ffma2(a0A, xA[r], w[r][0]);  ffma2(a0B, xB[r], w[r][0]);
        ffma2(a1A, xA[r], w[r][1]);  ffma2(a1B, xB[r], w[r][1]);
        ffma2(a2A, xA[r], w[r][2]);  ffma2(a2B, xB[r], w[r][2]);
    }

    float f0A = on ? fold2(a0A) : 0.f;
    float f1A = on ? fold2(a1A) : 0.f;
    float f2A = on ? fold2(a2A) : 0.f;
    float f0B = on ? fold2(a0B) : 0.f;
    float f1B = on ? fold2(a1B) : 0.f;
    float f2B = on ? fold2(a2B) : 0.f;

    // ---- packed butterfly reduction (3 chains for 6 partials) ----
    // Chain layout matches output pairs: pP0=(A.o0,A.o1), pP1=(A.o2,B.o0),
    // pP2=(B.o1,B.o2) -> lane k just unpacks chain k.
    u64 pP0 = pack2(f0A, f1A);
    u64 pP1 = pack2(f2A, f0B);
    u64 pP2 = pack2(f1B, f2B);
    #pragma unroll
    for (int off = 16; off; off >>= 1) {
        pP0 = fadd2(pP0, shfl_xor64(pP0, off));
        pP1 = fadd2(pP1, shfl_xor64(pP1, off));
        pP2 = fadd2(pP2, shfl_xor64(pP2, off));
    }

    if (lane < 3) {
        const u64 p = (lane == 0) ? pP0 : (lane == 1) ? pP1 : pP2;
        float ax, ay;
        asm("mov.b64 {%0,%1}, %2;" : "=f"(ax), "=f"(ay) : "l"(p));
        const float r0 = __expf(fminf(ax + bbx, 10.f)) * lgx;
        const float r1 = __expf(fminf(ay + bby, 10.f)) * lgy;
        *(u64*)(out + sA * 3 + lane * 2) = pack2(r0, r1);   // STG.64
    }
}

extern "C" void kernel_launch(void* const* d_in, const int* in_sizes, int n_in,
                              void* d_out, int out_size)
{
    const float* buffer = (const float*)d_in[0];
    const float* W      = (const float*)d_in[1];
    const float* bvec   = (const float*)d_in[2];
    const float* legal  = (const float*)d_in[3];
    const int*   bufidx = (const int*)d_in[4];
    const int*   stkidx = (const int*)d_in[5];
    float* out = (float*)d_out;

    tb_parser_kernel<<<CTAS, THR>>>(buffer, W, bvec, legal, bufidx, stkidx, out);
}